// round 13
// baseline (speedup 1.0000x reference)
#include <cuda_runtime.h>
#include <cuda_fp16.h>
#include <cfloat>
#include <cstdint>

#define BB 128
#define LQ 512
#define LK 512
#define DD 64
#define TQ 32
#define CK 128           // k rows per chunk
#define NCH (LK/CK)      // 4
#define PHS  520         // fp16 E stride (halves)
#define KS   72          // K/V fp16 row stride (halves)
#define QSP  68          // Q fp32 stride
#define OSP  68          // O-sum fp32 stride
#define NTHREADS 256

// smem byte offsets
#define OFF_E  0                           // 32*520*2 = 33280
#define OFF_K0 33280                       // 128*72*2 = 18432 (hi only)
#define OFF_K1 (OFF_K0 + 18432)            // 51712
#define OFF_V  (OFF_K1 + 18432)            // 70144, 18432
#define OFF_Q  (OFF_V + 18432)             // 88576, 32*68*4 = 8704
#define OFF_Z  (OFF_Q + 8704)              // 97280, 128
#define SMEM_BYTES (OFF_Z + 128)           // 97408
#define OFF_OS OFF_K0                      // O-sum aliases K0 after mainloop (32*68*4=8704)

__device__ float g_out_scratch[(size_t)BB * LQ * DD];

static __device__ __forceinline__ uint32_t s2u(const void* p) {
    uint32_t a;
    asm("{ .reg .u64 t; cvta.to.shared.u64 t, %1; cvt.u32.u64 %0, t; }" : "=r"(a) : "l"(p));
    return a;
}
static __device__ __forceinline__ uint32_t pack_hi(float x, float y) {
    __half2 h = __floats2half2_rn(x, y);
    return *(uint32_t*)&h;
}
static __device__ __forceinline__ uint32_t pack_lo(float x, float y, uint32_t hibits) {
    __half2 h = *(__half2*)&hibits;
    float2 hf = __half22float2(h);
    __half2 l = __floats2half2_rn(x - hf.x, y - hf.y);
    return *(uint32_t*)&l;
}
static __device__ __forceinline__ void mma16816(float& c0, float& c1, float& c2, float& c3,
                                                uint32_t a0, uint32_t a1, uint32_t a2, uint32_t a3,
                                                uint32_t b0, uint32_t b1) {
    asm volatile("mma.sync.aligned.m16n8k16.row.col.f32.f16.f16.f32 "
                 "{%0,%1,%2,%3}, {%4,%5,%6,%7}, {%8,%9}, {%0,%1,%2,%3};"
                 : "+f"(c0), "+f"(c1), "+f"(c2), "+f"(c3)
                 : "r"(a0), "r"(a1), "r"(a2), "r"(a3), "r"(b0), "r"(b1));
}
static __device__ __forceinline__ void ldsm4t(uint32_t& r0, uint32_t& r1, uint32_t& r2, uint32_t& r3,
                                              uint32_t addr) {
    asm volatile("ldmatrix.sync.aligned.m8n8.x4.trans.shared.b16 {%0,%1,%2,%3}, [%4];"
                 : "=r"(r0), "=r"(r1), "=r"(r2), "=r"(r3) : "r"(addr));
}

__global__ __launch_bounds__(NTHREADS, 2)
void sdpa_fused_kernel(const float* __restrict__ q,
                       const float* __restrict__ k,
                       const float* __restrict__ v,
                       const int* __restrict__ km,
                       const int* __restrict__ qm,
                       float* __restrict__ out,
                       float* __restrict__ attn)
{
    extern __shared__ char sm[];
    const uint32_t sbase = s2u(sm);
    float* Qs  = (float*)(sm + OFF_Q);
    float* Zsm = (float*)(sm + OFF_Z);

    const int t = threadIdx.x;
    const int w = t >> 5, l = t & 31;
    const int g = l >> 2, tq = l & 3;
    const int b = blockIdx.y;
    const int q0 = blockIdx.x * TQ;

    const float* kb = k + (size_t)b * LK * DD;
    const float* vb = v + (size_t)b * LK * DD;

    if (t < 32) Zsm[t] = 0.0f;

    // ---- stage Q (fp32) + K chunk 0 (hi fp16 only) ----
    {
        const float4* qg = (const float4*)(q + ((size_t)b * LQ + q0) * DD);
#pragma unroll
        for (int i = 0; i < 2; i++) {
            int idx = t + NTHREADS * i;
            float4 val = qg[idx];
            *(float4*)&Qs[(idx >> 4) * QSP + ((idx & 15) << 2)] = val;
        }
        const float4* kg = (const float4*)kb;
#pragma unroll
        for (int i = 0; i < 8; i++) {
            int idx = t + NTHREADS * i;            // 0..2047 (128 rows x 16 f4)
            float4 val = kg[idx];
            int krow = idx >> 4, d0 = (idx & 15) << 2;
            uint2 hi;
            hi.x = pack_hi(val.x, val.y); hi.y = pack_hi(val.z, val.w);
            *(uint2*)(sm + OFF_K0 + (krow * KS + d0) * 2) = hi;
        }
    }
    __syncthreads();

    // ---- warp roles: rg = row group (16 rows), ks = 32-col k-slice ----
    const int rg = w & 1, ks = w >> 1;
    const int r0i = rg * 16 + g, r1i = r0i + 8;

    // Q fragments (hi/lo fp16) for k=64
    uint32_t ahh[4][4], alo[4][4];
#pragma unroll
    for (int s = 0; s < 4; s++) {
        int k0 = 16 * s + 2 * tq;
        float2 p00 = *(float2*)&Qs[r0i * QSP + k0];
        float2 p01 = *(float2*)&Qs[r0i * QSP + k0 + 8];
        float2 p10 = *(float2*)&Qs[r1i * QSP + k0];
        float2 p11 = *(float2*)&Qs[r1i * QSP + k0 + 8];
        ahh[s][0] = pack_hi(p00.x, p00.y); alo[s][0] = pack_lo(p00.x, p00.y, ahh[s][0]);
        ahh[s][1] = pack_hi(p10.x, p10.y); alo[s][1] = pack_lo(p10.x, p10.y, ahh[s][1]);
        ahh[s][2] = pack_hi(p01.x, p01.y); alo[s][2] = pack_lo(p01.x, p01.y, ahh[s][2]);
        ahh[s][3] = pack_hi(p11.x, p11.y); alo[s][3] = pack_lo(p11.x, p11.y, ahh[s][3]);
    }

    const size_t growBase = (size_t)b * LQ + q0;
    const int mcol = ks * 32 + 2 * tq;
    const size_t mrow0 = (growBase + r0i) * LK + mcol;
    const size_t mrow1 = mrow0 + 8 * (size_t)LK;

    // E smem store bases (generic pointers!)
    char* e_r0 = sm + OFF_E + (r0i * PHS + mcol) * 2;
    char* e_r1 = e_r0 + 8 * (PHS * 2);

    float Z0 = 0.0f, Z1 = 0.0f;
    float on[8][4];
#pragma unroll
    for (int j = 0; j < 8; j++)
#pragma unroll
        for (int u = 0; u < 4; u++) on[j][u] = 0.0f;

    // =================== fused mainloop over 4 chunks of 128 k ===================
    for (int c = 0; c < NCH; c++) {
        // ---- masks for this chunk (issue early; consumed after S-MMA) ----
        uint32_t kmb = 0, qmb = 0;
        const int coff = c * CK;
#pragma unroll
        for (int j = 0; j < 4; j++) {
            int2 ka = *(const int2*)(km + mrow0 + coff + j * 8);
            int2 kbm = *(const int2*)(km + mrow1 + coff + j * 8);
            int2 qa = *(const int2*)(qm + mrow0 + coff + j * 8);
            int2 qbm = *(const int2*)(qm + mrow1 + coff + j * 8);
            kmb |= (ka.x ? 1u : 0u) << (2 * j) | (ka.y ? 2u : 0u) << (2 * j)
                 | (kbm.x ? 1u : 0u) << (8 + 2 * j) | (kbm.y ? 2u : 0u) << (8 + 2 * j);
            qmb |= (qa.x ? 1u : 0u) << (2 * j) | (qa.y ? 2u : 0u) << (2 * j)
                 | (qbm.x ? 1u : 0u) << (8 + 2 * j) | (qbm.y ? 2u : 0u) << (8 + 2 * j);
        }

        // ---- V chunk c: issue loads first half ----
        const float4* vg = (const float4*)(vb + (size_t)c * CK * DD);
        float4 vp[4];
#pragma unroll
        for (int i = 0; i < 4; i++) vp[i] = vg[t + NTHREADS * i];

        // ---- S = Q K^T over this warp's 32-col slice (2 passes) ----
        const char* kbuf = sm + ((c & 1) ? OFF_K1 : OFF_K0);
        float s0[4][4], s1[4][4];
#pragma unroll
        for (int j = 0; j < 4; j++)
#pragma unroll
            for (int u = 0; u < 4; u++) { s0[j][u] = 0.0f; s1[j][u] = 0.0f; }

#pragma unroll
        for (int s = 0; s < 4; s++) {
#pragma unroll
            for (int j = 0; j < 4; j++) {
                int row = ks * 32 + j * 8 + g;          // K row = S col
                int byte = (row * KS + 16 * s + 2 * tq) * 2;
                uint32_t bh0 = *(const uint32_t*)(kbuf + byte);
                uint32_t bh1 = *(const uint32_t*)(kbuf + byte + 16);
                mma16816(s0[j][0], s0[j][1], s0[j][2], s0[j][3],
                         ahh[s][0], ahh[s][1], ahh[s][2], ahh[s][3], bh0, bh1);
                mma16816(s1[j][0], s1[j][1], s1[j][2], s1[j][3],
                         alo[s][0], alo[s][1], alo[s][2], alo[s][3], bh0, bh1);
            }
        }

        // ---- exp + masks + Z + E fragments (rows g / g+8) ----
        uint32_t er0[4], er1[4];
#pragma unroll
        for (int j = 0; j < 4; j++) {
            float a0 = s0[j][0] + s1[j][0];
            float a1 = s0[j][1] + s1[j][1];
            float a2 = s0[j][2] + s1[j][2];
            float a3 = s0[j][3] + s1[j][3];
            float e00 = (kmb & (1u << (2 * j)))      ? 0.0f : __expf(a0 * 0.125f);
            float e01 = (kmb & (2u << (2 * j)))      ? 0.0f : __expf(a1 * 0.125f);
            float e10 = (kmb & (1u << (8 + 2 * j)))  ? 0.0f : __expf(a2 * 0.125f);
            float e11 = (kmb & (2u << (8 + 2 * j)))  ? 0.0f : __expf(a3 * 0.125f);
            Z0 += e00 + e01;
            Z1 += e10 + e11;
            float m00 = (qmb & (1u << (2 * j)))     ? 0.0f : e00;
            float m01 = (qmb & (2u << (2 * j)))     ? 0.0f : e01;
            float m10 = (qmb & (1u << (8 + 2 * j))) ? 0.0f : e10;
            float m11 = (qmb & (2u << (8 + 2 * j))) ? 0.0f : e11;
            er0[j] = pack_hi(m00, m01);
            er1[j] = pack_hi(m10, m11);
            int cofs = (coff + j * 8) * 2;
            *(uint32_t*)(e_r0 + cofs) = er0[j];
            *(uint32_t*)(e_r1 + cofs) = er1[j];
        }

        // ---- finish V staging ----
#pragma unroll
        for (int i = 0; i < 4; i++) {
            int idx = t + NTHREADS * i;
            int krow = idx >> 4, d0 = (idx & 15) << 2;
            uint2 h;
            h.x = pack_hi(vp[i].x, vp[i].y); h.y = pack_hi(vp[i].z, vp[i].w);
            *(uint2*)(sm + OFF_V + (krow * KS + d0) * 2) = h;
        }
#pragma unroll
        for (int i = 4; i < 8; i++) {
            int idx = t + NTHREADS * i;
            float4 val = vg[idx];
            int krow = idx >> 4, d0 = (idx & 15) << 2;
            uint2 h;
            h.x = pack_hi(val.x, val.y); h.y = pack_hi(val.z, val.w);
            *(uint2*)(sm + OFF_V + (krow * KS + d0) * 2) = h;
        }
        __syncthreads();   // V_c staged (E not needed cross-warp here)

        // ---- O-MMA: A = E fragments (in regs!), B = V^T ----
#pragma unroll
        for (int s2 = 0; s2 < 2; s2++) {
            uint32_t a0 = er0[2 * s2], a1 = er1[2 * s2];
            uint32_t a2 = er0[2 * s2 + 1], a3 = er1[2 * s2 + 1];
#pragma unroll
            for (int i = 0; i < 4; i++) {
                uint32_t b0, b1, b2, b3;
                uint32_t addr = sbase + OFF_V
                    + ((ks * 32 + s2 * 16 + (l & 15)) * KS) * 2
                    + (i * 16 + ((l >> 4) & 1) * 8) * 2;
                ldsm4t(b0, b1, b2, b3, addr);
                mma16816(on[2 * i][0], on[2 * i][1], on[2 * i][2], on[2 * i][3],
                         a0, a1, a2, a3, b0, b1);
                mma16816(on[2 * i + 1][0], on[2 * i + 1][1], on[2 * i + 1][2], on[2 * i + 1][3],
                         a0, a1, a2, a3, b2, b3);
            }
        }

        // ---- stage K chunk c+1 ----
        if (c + 1 < NCH) {
            const float4* kg2 = (const float4*)(kb + (size_t)(c + 1) * CK * DD);
            char* nbuf = sm + (((c + 1) & 1) ? OFF_K1 : OFF_K0);
#pragma unroll
            for (int i = 0; i < 8; i++) {
                int idx = t + NTHREADS * i;
                float4 val = kg2[idx];
                int krow = idx >> 4, d0 = (idx & 15) << 2;
                uint2 h;
                h.x = pack_hi(val.x, val.y); h.y = pack_hi(val.z, val.w);
                *(uint2*)(nbuf + (krow * KS + d0) * 2) = h;
            }
        }
        __syncthreads();   // K_{c+1} staged / K buffer protect
    }

    // ---- Z reduction ----
    Z0 += __shfl_xor_sync(0xffffffffu, Z0, 1);
    Z0 += __shfl_xor_sync(0xffffffffu, Z0, 2);
    Z1 += __shfl_xor_sync(0xffffffffu, Z1, 1);
    Z1 += __shfl_xor_sync(0xffffffffu, Z1, 2);
    if (tq == 0) {
        atomicAdd(&Zsm[r0i], Z0);
        atomicAdd(&Zsm[r1i], Z1);
    }
    // zero O-sum region (aliases K0; last K read done)
    float* Osum = (float*)(sm + OFF_OS);
    for (int i = t; i < TQ * OSP; i += NTHREADS) Osum[i] = 0.0f;
    __syncthreads();

    if (t < 32) Zsm[t] = 1.0f / Zsm[t];
    // accumulate per-warp partial O
#pragma unroll
    for (int j = 0; j < 8; j++) {
        atomicAdd(&Osum[r0i * OSP + j * 8 + 2 * tq],     on[j][0]);
        atomicAdd(&Osum[r0i * OSP + j * 8 + 2 * tq + 1], on[j][1]);
        atomicAdd(&Osum[r1i * OSP + j * 8 + 2 * tq],     on[j][2]);
        atomicAdd(&Osum[r1i * OSP + j * 8 + 2 * tq + 1], on[j][3]);
    }
    __syncthreads();

    // ---- write O (coalesced) ----
    {
        int row = t >> 3, cb = (t & 7) * 8;
        float invZ = Zsm[row];
        float4 o0 = *(float4*)&Osum[row * OSP + cb];
        float4 o1 = *(float4*)&Osum[row * OSP + cb + 4];
        float* orow = out + (growBase + row) * DD + cb;
        *(float4*)orow = make_float4(o0.x * invZ, o0.y * invZ, o0.z * invZ, o0.w * invZ);
        *(float4*)(orow + 4) = make_float4(o1.x * invZ, o1.y * invZ, o1.z * invZ, o1.w * invZ);
    }

    // ---- write attn = E * invZ (fp32, coalesced) ----
    if (attn) {
#pragma unroll
        for (int rr = 0; rr < 4; rr++) {
            const int r = w + (rr << 3);
            const float invZ = Zsm[r];
            float* arow = attn + (growBase + r) * LK;
#pragma unroll
            for (int j = 0; j < 4; j++) {
                int col = 4 * l + 128 * j;
                uint2 hh = *(const uint2*)(sm + OFF_E + (r * PHS + col) * 2);
                float2 f0 = __half22float2(*(__half2*)&hh.x);
                float2 f1 = __half22float2(*(__half2*)&hh.y);
                *(float4*)(arow + col) = make_float4(f0.x * invZ, f0.y * invZ,
                                                     f1.x * invZ, f1.y * invZ);
            }
        }
    }
}

extern "C" void kernel_launch(void* const* d_in, const int* in_sizes, int n_in,
                              void* d_out, int out_size)
{
    const float* q = (const float*)d_in[0];
    const float* k = (const float*)d_in[1];
    const float* v = (const float*)d_in[2];
    const int* km = (const int*)d_in[3];
    const int* qm = (const int*)d_in[4];

    const long long OUT_N  = (long long)BB * LQ * DD;
    const long long ATTN_N = (long long)BB * LQ * LK;

    float* out_p;
    float* attn_p;
    long long osz = (long long)out_size;
    if (osz >= OUT_N + ATTN_N) {
        out_p  = (float*)d_out;
        attn_p = (float*)d_out + OUT_N;
    } else if (osz == ATTN_N) {
        float* scratch;
        cudaGetSymbolAddress((void**)&scratch, g_out_scratch);
        out_p  = scratch;
        attn_p = (float*)d_out;
    } else {
        out_p  = (float*)d_out;
        attn_p = nullptr;
    }

    cudaFuncSetAttribute(sdpa_fused_kernel, cudaFuncAttributeMaxDynamicSharedMemorySize, SMEM_BYTES);
    dim3 grid(LQ / TQ, BB);
    sdpa_fused_kernel<<<grid, NTHREADS, SMEM_BYTES>>>(q, k, v, km, qm, out_p, attn_p);
}

// round 14
// speedup vs baseline: 1.0591x; 1.0591x over previous
#include <cuda_runtime.h>
#include <cuda_fp16.h>
#include <cfloat>
#include <cstdint>

#define BB 128
#define LQ 512
#define LK 512
#define DD 64
#define TQ 32
#define TK 64
#define NCH (LK/TK)          // 8
#define PHS  520             // fp16 E stride (halves)
#define KS   72              // K/V fp16 row stride (halves) -> 144 B/row
#define QSP  68              // Q fp32 stride
#define NTHREADS 256

// smem byte offsets
#define OFF_E  0                           // 32*520*2 = 33280
#define KBUF   9216                        // 64*72*2
#define OFF_K0 33280                       // 3 buffers -> 27648
#define OFF_Q  (OFF_K0 + 3*KBUF)           // 60928, 8704
#define OFF_Z  (OFF_Q + 8704)              // 69632, 128
#define SMEM_BYTES (OFF_Z + 128)           // 69760

__device__ float g_out_scratch[(size_t)BB * LQ * DD];
__device__ __half g_khi[(size_t)BB * LK * DD];   // 8 MB
__device__ __half g_vh [(size_t)BB * LK * DD];   // 8 MB

static __device__ __forceinline__ uint32_t s2u(const void* p) {
    uint32_t a;
    asm("{ .reg .u64 t; cvta.to.shared.u64 t, %1; cvt.u32.u64 %0, t; }" : "=r"(a) : "l"(p));
    return a;
}
static __device__ __forceinline__ uint32_t pack_hi(float x, float y) {
    __half2 h = __floats2half2_rn(x, y);
    return *(uint32_t*)&h;
}
static __device__ __forceinline__ uint32_t pack_lo(float x, float y, uint32_t hibits) {
    __half2 h = *(__half2*)&hibits;
    float2 hf = __half22float2(h);
    __half2 l = __floats2half2_rn(x - hf.x, y - hf.y);
    return *(uint32_t*)&l;
}
static __device__ __forceinline__ void mma16816(float& c0, float& c1, float& c2, float& c3,
                                                uint32_t a0, uint32_t a1, uint32_t a2, uint32_t a3,
                                                uint32_t b0, uint32_t b1) {
    asm volatile("mma.sync.aligned.m16n8k16.row.col.f32.f16.f16.f32 "
                 "{%0,%1,%2,%3}, {%4,%5,%6,%7}, {%8,%9}, {%0,%1,%2,%3};"
                 : "+f"(c0), "+f"(c1), "+f"(c2), "+f"(c3)
                 : "r"(a0), "r"(a1), "r"(a2), "r"(a3), "r"(b0), "r"(b1));
}
static __device__ __forceinline__ void ldsm4(uint32_t& r0, uint32_t& r1, uint32_t& r2, uint32_t& r3,
                                             uint32_t addr) {
    asm volatile("ldmatrix.sync.aligned.m8n8.x4.shared.b16 {%0,%1,%2,%3}, [%4];"
                 : "=r"(r0), "=r"(r1), "=r"(r2), "=r"(r3) : "r"(addr));
}
static __device__ __forceinline__ void ldsm4t(uint32_t& r0, uint32_t& r1, uint32_t& r2, uint32_t& r3,
                                              uint32_t addr) {
    asm volatile("ldmatrix.sync.aligned.m8n8.x4.trans.shared.b16 {%0,%1,%2,%3}, [%4];"
                 : "=r"(r0), "=r"(r1), "=r"(r2), "=r"(r3) : "r"(addr));
}
static __device__ __forceinline__ void cpa16(uint32_t dst, const void* src) {
    asm volatile("cp.async.ca.shared.global [%0], [%1], 16;" :: "r"(dst), "l"(src));
}
#define CPA_COMMIT() asm volatile("cp.async.commit_group;" ::: "memory")
#define CPA_WAIT0()  asm volatile("cp.async.wait_group 0;" ::: "memory")
#define CPA_WAIT1()  asm volatile("cp.async.wait_group 1;" ::: "memory")

// stage one 64x64 fp16 tile (row 128B in gmem -> stride 144B in smem), 2x16B per thread
static __device__ __forceinline__ void stage_tile(const __half* src, uint32_t dstbase, int t) {
    int row = t >> 2;
    int off = (t & 3) * 32;
    const char* s = (const char*)src + row * 128 + off;
    uint32_t d = dstbase + row * 144 + off;
    cpa16(d, s);
    cpa16(d + 16, s + 16);
}
// pack 8 mask ints (two rows x 2 nt x 2 cols) into one bitmask
static __device__ __forceinline__ uint32_t pack_mask8(const int* p, size_t r0, size_t r1, int off) {
    int2 a = *(const int2*)(p + r0 + off);
    int2 b = *(const int2*)(p + r0 + off + 8);
    int2 c = *(const int2*)(p + r1 + off);
    int2 d = *(const int2*)(p + r1 + off + 8);
    return (a.x ? 1u : 0u) | (a.y ? 2u : 0u) | (b.x ? 4u : 0u) | (b.y ? 8u : 0u)
         | (c.x ? 16u : 0u) | (c.y ? 32u : 0u) | (d.x ? 64u : 0u) | (d.y ? 128u : 0u);
}

// ---------------- prepass: fp32 -> fp16 for K and V ----------------
__global__ void cvt_kv_kernel(const float* __restrict__ k, const float* __restrict__ v,
                              __half* __restrict__ kh, __half* __restrict__ vh) {
    int i = blockIdx.x * blockDim.x + threadIdx.x;            // float4 index
    const int n4 = BB * LK * DD / 4;
    if (i < n4) {
        float4 a = ((const float4*)k)[i];
        ((uint2*)kh)[i] = make_uint2(pack_hi(a.x, a.y), pack_hi(a.z, a.w));
        float4 b = ((const float4*)v)[i];
        ((uint2*)vh)[i] = make_uint2(pack_hi(b.x, b.y), pack_hi(b.z, b.w));
    }
}

__global__ __launch_bounds__(NTHREADS, 2)
void sdpa_flash_kernel(const float* __restrict__ q,
                       const __half* __restrict__ khi,
                       const __half* __restrict__ vh,
                       const int* __restrict__ km,
                       const int* __restrict__ qm,
                       float* __restrict__ out,
                       float* __restrict__ attn)
{
    extern __shared__ char sm[];
    const uint32_t sbase = s2u(sm);
    float* Qs  = (float*)(sm + OFF_Q);
    float* Zsm = (float*)(sm + OFF_Z);

    const int t = threadIdx.x;
    const int w = t >> 5, l = t & 31;
    const int g = l >> 2, tq = l & 3;
    const int b = blockIdx.y;
    const int q0 = blockIdx.x * TQ;

    const __half* kb = khi + (size_t)b * LK * DD;
    const __half* vb = vh + (size_t)b * LK * DD;

    if (t < 32) Zsm[t] = 0.0f;

    // issue K chunk 0 via cp.async, then stage Q while it flies
    stage_tile(kb, sbase + OFF_K0, t);
    CPA_COMMIT();
    {
        const float4* qg = (const float4*)(q + ((size_t)b * LQ + q0) * DD);
#pragma unroll
        for (int i = 0; i < 2; i++) {
            int idx = t + NTHREADS * i;
            float4 val = qg[idx];
            *(float4*)&Qs[(idx >> 4) * QSP + ((idx & 15) << 2)] = val;
        }
    }
    __syncthreads();

    // ---- warp roles + Q fragments (hi/lo) ----
    const int rg = w & 1, cg = w >> 1;
    const int r0i = rg * 16 + g, r1i = r0i + 8;
    uint32_t ahh[4][4], alo[4][4];
#pragma unroll
    for (int s = 0; s < 4; s++) {
        int k0 = 16 * s + 2 * tq;
        float2 p00 = *(float2*)&Qs[r0i * QSP + k0];
        float2 p01 = *(float2*)&Qs[r0i * QSP + k0 + 8];
        float2 p10 = *(float2*)&Qs[r1i * QSP + k0];
        float2 p11 = *(float2*)&Qs[r1i * QSP + k0 + 8];
        ahh[s][0] = pack_hi(p00.x, p00.y); alo[s][0] = pack_lo(p00.x, p00.y, ahh[s][0]);
        ahh[s][1] = pack_hi(p10.x, p10.y); alo[s][1] = pack_lo(p10.x, p10.y, ahh[s][1]);
        ahh[s][2] = pack_hi(p01.x, p01.y); alo[s][2] = pack_lo(p01.x, p01.y, ahh[s][2]);
        ahh[s][3] = pack_hi(p11.x, p11.y); alo[s][3] = pack_lo(p11.x, p11.y, ahh[s][3]);
    }

    const size_t growBase = (size_t)b * LQ + q0;
    const size_t mrow0 = (growBase + r0i) * LK + cg * 16 + 2 * tq;
    const size_t mrow1 = mrow0 + 8 * (size_t)LK;

    uint32_t kmb = pack_mask8(km, mrow0, mrow1, 0);
    uint32_t qmb = pack_mask8(qm, mrow0, mrow1, 0);

    float Z0 = 0.0f, Z1 = 0.0f;
    char* e_r0 = sm + OFF_E + (r0i * PHS + (cg * 16 + 2 * tq)) * 2;
    char* e_r1 = e_r0 + 8 * (PHS * 2);

    // =================== Phase 1: E = exp(mask(Q K^T / 8)) ===================
    for (int c = 0; c < NCH; c++) {
        uint32_t kmn = 0, qmn = 0;
        if (c + 1 < NCH) {
            stage_tile(kb + (size_t)(c + 1) * TK * DD,
                       sbase + OFF_K0 + ((c + 1) % 3) * KBUF, t);
            CPA_COMMIT();
            CPA_WAIT1();
        } else {
            CPA_WAIT0();
        }
        __syncthreads();                       // buf c ready for all warps

        if (c + 1 < NCH) {                     // mask prefetch overlaps MMA
            int off = (c + 1) * TK;
            kmn = pack_mask8(km, mrow0, mrow1, off);
            qmn = pack_mask8(qm, mrow0, mrow1, off);
        }

        const char* kbuf = sm + OFF_K0 + (c % 3) * KBUF;
        float ac0[2][4], ac1[2][4];
#pragma unroll
        for (int nt = 0; nt < 2; nt++)
#pragma unroll
            for (int j = 0; j < 4; j++) { ac0[nt][j] = 0.0f; ac1[nt][j] = 0.0f; }

#pragma unroll
        for (int s = 0; s < 4; s++) {
#pragma unroll
            for (int nt = 0; nt < 2; nt++) {
                int row = cg * 16 + nt * 8 + g;
                int byte = (row * KS + 16 * s + 2 * tq) * 2;
                uint32_t bh0 = *(const uint32_t*)(kbuf + byte);
                uint32_t bh1 = *(const uint32_t*)(kbuf + byte + 16);
                mma16816(ac0[nt][0], ac0[nt][1], ac0[nt][2], ac0[nt][3],
                         ahh[s][0], ahh[s][1], ahh[s][2], ahh[s][3], bh0, bh1);
                mma16816(ac1[nt][0], ac1[nt][1], ac1[nt][2], ac1[nt][3],
                         alo[s][0], alo[s][1], alo[s][2], alo[s][3], bh0, bh1);
            }
        }

        // mask + exp + Z + fp16 E store
#pragma unroll
        for (int nt = 0; nt < 2; nt++) {
            float a0 = ac0[nt][0] + ac1[nt][0];
            float a1 = ac0[nt][1] + ac1[nt][1];
            float a2 = ac0[nt][2] + ac1[nt][2];
            float a3 = ac0[nt][3] + ac1[nt][3];
            float e00 = (kmb & (1u << (2 * nt)))  ? 0.0f : __expf(a0 * 0.125f);
            float e01 = (kmb & (2u << (2 * nt)))  ? 0.0f : __expf(a1 * 0.125f);
            float e10 = (kmb & (16u << (2 * nt))) ? 0.0f : __expf(a2 * 0.125f);
            float e11 = (kmb & (32u << (2 * nt))) ? 0.0f : __expf(a3 * 0.125f);
            Z0 += e00 + e01;
            Z1 += e10 + e11;
            float s00 = (qmb & (1u << (2 * nt)))  ? 0.0f : e00;
            float s01 = (qmb & (2u << (2 * nt)))  ? 0.0f : e01;
            float s10 = (qmb & (16u << (2 * nt))) ? 0.0f : e10;
            float s11 = (qmb & (32u << (2 * nt))) ? 0.0f : e11;
            int cofs = (c * TK + nt * 8) * 2;
            *(uint32_t*)(e_r0 + cofs) = pack_hi(s00, s01);
            *(uint32_t*)(e_r1 + cofs) = pack_hi(s10, s11);
        }
        kmb = kmn; qmb = qmn;
    }

    // ---- Z reduction ----
    Z0 += __shfl_xor_sync(0xffffffffu, Z0, 1);
    Z0 += __shfl_xor_sync(0xffffffffu, Z0, 2);
    Z1 += __shfl_xor_sync(0xffffffffu, Z1, 1);
    Z1 += __shfl_xor_sync(0xffffffffu, Z1, 2);
    if (tq == 0) {
        atomicAdd(&Zsm[r0i], Z0);
        atomicAdd(&Zsm[r1i], Z1);
    }
    __syncthreads();
    if (t < 32) Zsm[t] = 1.0f / Zsm[t];

    // issue V chunk 0 (K buf 0 free: all warps past phase-1 end)
    stage_tile(vb, sbase + OFF_K0, t);
    CPA_COMMIT();
    __syncthreads();                            // Zsm visible

    // ---- attn = E * invZ (overlaps V chunk-0 arrival) ----
    if (attn) {
#pragma unroll
        for (int rr = 0; rr < 4; rr++) {
            const int r = w + (rr << 3);
            const float invZ = Zsm[r];
            float* arow = attn + (growBase + r) * LK;
#pragma unroll
            for (int j = 0; j < 4; j++) {
                int col = 4 * l + 128 * j;
                uint2 hh = *(const uint2*)(sm + OFF_E + (r * PHS + col) * 2);
                float2 f0 = __half22float2(*(__half2*)&hh.x);
                float2 f1 = __half22float2(*(__half2*)&hh.y);
                *(float4*)(arow + col) = make_float4(f0.x * invZ, f0.y * invZ,
                                                     f1.x * invZ, f1.y * invZ);
            }
        }
    }

    // =================== Phase 2: O = (E V) * invZ ===================
    const int rg2 = w & 1, cg2 = w >> 1;
    float oe[2][4], oo[2][4];
#pragma unroll
    for (int nt = 0; nt < 2; nt++)
#pragma unroll
        for (int j = 0; j < 4; j++) { oe[nt][j] = 0.0f; oo[nt][j] = 0.0f; }

    const uint32_t a_base = sbase + OFF_E + (rg2 * 16 + (l & 15)) * (PHS * 2) + ((l >> 4) & 1) * 16;
    const uint32_t b_coloff = (cg2 * 16 + ((l >> 4) & 1) * 8) * 2;

    for (int c = 0; c < NCH; c++) {
        if (c + 1 < NCH) {
            stage_tile(vb + (size_t)(c + 1) * TK * DD,
                       sbase + OFF_K0 + ((c + 1) % 3) * KBUF, t);
            CPA_COMMIT();
            CPA_WAIT1();
        } else {
            CPA_WAIT0();
        }
        __syncthreads();

        const uint32_t vbuf = sbase + OFF_K0 + (c % 3) * KBUF;
#pragma unroll
        for (int s = 0; s < 4; s++) {
            uint32_t a0, a1, a2, a3, b0, b1, b2, b3;
            ldsm4(a0, a1, a2, a3, a_base + (c * TK + s * 16) * 2);
            ldsm4t(b0, b1, b2, b3, vbuf + (s * 16 + (l & 15)) * (KS * 2) + b_coloff);
            if (s & 1) {
                mma16816(oo[0][0], oo[0][1], oo[0][2], oo[0][3], a0, a1, a2, a3, b0, b1);
                mma16816(oo[1][0], oo[1][1], oo[1][2], oo[1][3], a0, a1, a2, a3, b2, b3);
            } else {
                mma16816(oe[0][0], oe[0][1], oe[0][2], oe[0][3], a0, a1, a2, a3, b0, b1);
                mma16816(oe[1][0], oe[1][1], oe[1][2], oe[1][3], a0, a1, a2, a3, b2, b3);
            }
        }
    }

    // write O with per-row 1/Z
    {
        const int row0 = rg2 * 16 + g;
        const float invZa = Zsm[row0], invZb = Zsm[row0 + 8];
#pragma unroll
        for (int nt = 0; nt < 2; nt++) {
            int col = cg2 * 16 + nt * 8 + 2 * tq;
            *(float2*)(out + (growBase + row0) * DD + col) =
                make_float2((oe[nt][0] + oo[nt][0]) * invZa, (oe[nt][1] + oo[nt][1]) * invZa);
            *(float2*)(out + (growBase + row0 + 8) * DD + col) =
                make_float2((oe[nt][2] + oo[nt][2]) * invZb, (oe[nt][3] + oo[nt][3]) * invZb);
        }
    }
}

extern "C" void kernel_launch(void* const* d_in, const int* in_sizes, int n_in,
                              void* d_out, int out_size)
{
    const float* q = (const float*)d_in[0];
    const float* k = (const float*)d_in[1];
    const float* v = (const float*)d_in[2];
    const int* km = (const int*)d_in[3];
    const int* qm = (const int*)d_in[4];

    const long long OUT_N  = (long long)BB * LQ * DD;
    const long long ATTN_N = (long long)BB * LQ * LK;

    float* out_p;
    float* attn_p;
    long long osz = (long long)out_size;
    if (osz >= OUT_N + ATTN_N) {
        out_p  = (float*)d_out;
        attn_p = (float*)d_out + OUT_N;
    } else if (osz == ATTN_N) {
        float* scratch;
        cudaGetSymbolAddress((void**)&scratch, g_out_scratch);
        out_p  = scratch;
        attn_p = (float*)d_out;
    } else {
        out_p  = (float*)d_out;
        attn_p = nullptr;
    }

    __half* khi_p;
    __half* vh_p;
    cudaGetSymbolAddress((void**)&khi_p, g_khi);
    cudaGetSymbolAddress((void**)&vh_p, g_vh);

    // prepass: K/V fp32 -> fp16 (once)
    {
        const int n4 = BB * LK * DD / 4;
        cvt_kv_kernel<<<(n4 + 255) / 256, 256>>>(k, v, khi_p, vh_p);
    }

    cudaFuncSetAttribute(sdpa_flash_kernel, cudaFuncAttributeMaxDynamicSharedMemorySize, SMEM_BYTES);
    dim3 grid(LQ / TQ, BB);
    sdpa_flash_kernel<<<grid, NTHREADS, SMEM_BYTES>>>(q, khi_p, vh_p, km, qm, out_p, attn_p);
}

// round 16
// speedup vs baseline: 1.0653x; 1.0059x over previous
#include <cuda_runtime.h>
#include <cuda_fp16.h>
#include <cfloat>
#include <cstdint>

#define BB 128
#define LQ 512
#define LK 512
#define DD 64
#define TQ 32
#define TK 64
#define NCH (LK/TK)          // 8
#define PHS  520             // fp16 E stride (halves)
#define KS   72              // K/V fp16 row stride (halves) -> 144 B/row
#define QSP  68              // Q fp32 stride
#define NTHREADS 256

// smem byte offsets
#define OFF_E  0                           // 32*520*2 = 33280
#define KBUF   9216                        // 64*72*2
#define OFF_K0 33280                       // 3 buffers -> 27648
#define OFF_Q  (OFF_K0 + 3*KBUF)           // 60928, 8704
#define OFF_Z  (OFF_Q + 8704)              // 69632, 128
#define SMEM_BYTES (OFF_Z + 128)           // 69760  (x3 = 209280 <= 228KB)

__device__ float g_out_scratch[(size_t)BB * LQ * DD];
__device__ __half g_khi[(size_t)BB * LK * DD];   // 8 MB
__device__ __half g_vh [(size_t)BB * LK * DD];   // 8 MB

static __device__ __forceinline__ uint32_t s2u(const void* p) {
    uint32_t a;
    asm("{ .reg .u64 t; cvta.to.shared.u64 t, %1; cvt.u32.u64 %0, t; }" : "=r"(a) : "l"(p));
    return a;
}
static __device__ __forceinline__ uint32_t pack_hi(float x, float y) {
    __half2 h = __floats2half2_rn(x, y);
    return *(uint32_t*)&h;
}
static __device__ __forceinline__ uint32_t pack_lo(float x, float y, uint32_t hibits) {
    __half2 h = *(__half2*)&hibits;
    float2 hf = __half22float2(h);
    __half2 l = __floats2half2_rn(x - hf.x, y - hf.y);
    return *(uint32_t*)&l;
}
static __device__ __forceinline__ void mma16816(float& c0, float& c1, float& c2, float& c3,
                                                uint32_t a0, uint32_t a1, uint32_t a2, uint32_t a3,
                                                uint32_t b0, uint32_t b1) {
    asm volatile("mma.sync.aligned.m16n8k16.row.col.f32.f16.f16.f32 "
                 "{%0,%1,%2,%3}, {%4,%5,%6,%7}, {%8,%9}, {%0,%1,%2,%3};"
                 : "+f"(c0), "+f"(c1), "+f"(c2), "+f"(c3)
                 : "r"(a0), "r"(a1), "r"(a2), "r"(a3), "r"(b0), "r"(b1));
}
static __device__ __forceinline__ void ldsm4(uint32_t& r0, uint32_t& r1, uint32_t& r2, uint32_t& r3,
                                             uint32_t addr) {
    asm volatile("ldmatrix.sync.aligned.m8n8.x4.shared.b16 {%0,%1,%2,%3}, [%4];"
                 : "=r"(r0), "=r"(r1), "=r"(r2), "=r"(r3) : "r"(addr));
}
static __device__ __forceinline__ void ldsm4t(uint32_t& r0, uint32_t& r1, uint32_t& r2, uint32_t& r3,
                                              uint32_t addr) {
    asm volatile("ldmatrix.sync.aligned.m8n8.x4.trans.shared.b16 {%0,%1,%2,%3}, [%4];"
                 : "=r"(r0), "=r"(r1), "=r"(r2), "=r"(r3) : "r"(addr));
}
static __device__ __forceinline__ void cpa16(uint32_t dst, const void* src) {
    asm volatile("cp.async.ca.shared.global [%0], [%1], 16;" :: "r"(dst), "l"(src));
}
#define CPA_COMMIT() asm volatile("cp.async.commit_group;" ::: "memory")
#define CPA_WAIT0()  asm volatile("cp.async.wait_group 0;" ::: "memory")
#define CPA_WAIT1()  asm volatile("cp.async.wait_group 1;" ::: "memory")

// stage one 64x64 fp16 tile (row 128B in gmem -> stride 144B in smem), 2x16B per thread
static __device__ __forceinline__ void stage_tile(const __half* src, uint32_t dstbase, int t) {
    int row = t >> 2;
    int off = (t & 3) * 32;
    const char* s = (const char*)src + row * 128 + off;
    uint32_t d = dstbase + row * 144 + off;
    cpa16(d, s);
    cpa16(d + 16, s + 16);
}
// pack 8 mask ints (two rows x 2 nt x 2 cols) into one bitmask
static __device__ __forceinline__ uint32_t pack_mask8(const int* p, size_t r0, size_t r1, int off) {
    int2 a = *(const int2*)(p + r0 + off);
    int2 b = *(const int2*)(p + r0 + off + 8);
    int2 c = *(const int2*)(p + r1 + off);
    int2 d = *(const int2*)(p + r1 + off + 8);
    return (a.x ? 1u : 0u) | (a.y ? 2u : 0u) | (b.x ? 4u : 0u) | (b.y ? 8u : 0u)
         | (c.x ? 16u : 0u) | (c.y ? 32u : 0u) | (d.x ? 64u : 0u) | (d.y ? 128u : 0u);
}

// ---------------- prepass: fp32 -> fp16 for K and V (grid-stride) ----------------
__global__ void cvt_kv_kernel(const float* __restrict__ k, const float* __restrict__ v,
                              __half* __restrict__ kh, __half* __restrict__ vh) {
    const int n4 = BB * LK * DD / 4;
    for (int i = blockIdx.x * blockDim.x + threadIdx.x; i < n4; i += gridDim.x * blockDim.x) {
        float4 a = ((const float4*)k)[i];
        ((uint2*)kh)[i] = make_uint2(pack_hi(a.x, a.y), pack_hi(a.z, a.w));
        float4 b = ((const float4*)v)[i];
        ((uint2*)vh)[i] = make_uint2(pack_hi(b.x, b.y), pack_hi(b.z, b.w));
    }
}

__global__ __launch_bounds__(NTHREADS, 3)
void sdpa_flash_kernel(const float* __restrict__ q,
                       const __half* __restrict__ khi,
                       const __half* __restrict__ vh,
                       const int* __restrict__ km,
                       const int* __restrict__ qm,
                       float* __restrict__ out,
                       float* __restrict__ attn)
{
    extern __shared__ char sm[];
    const uint32_t sbase = s2u(sm);
    float* Qs  = (float*)(sm + OFF_Q);
    float* Zsm = (float*)(sm + OFF_Z);

    const int t = threadIdx.x;
    const int w = t >> 5, l = t & 31;
    const int g = l >> 2, tq = l & 3;
    const int b = blockIdx.y;
    const int q0 = blockIdx.x * TQ;

    const __half* kb = khi + (size_t)b * LK * DD;
    const __half* vb = vh + (size_t)b * LK * DD;

    if (t < 32) Zsm[t] = 0.0f;

    // issue K chunk 0 via cp.async, then stage Q while it flies
    stage_tile(kb, sbase + OFF_K0, t);
    CPA_COMMIT();
    {
        const float4* qg = (const float4*)(q + ((size_t)b * LQ + q0) * DD);
#pragma unroll
        for (int i = 0; i < 2; i++) {
            int idx = t + NTHREADS * i;
            float4 val = qg[idx];
            *(float4*)&Qs[(idx >> 4) * QSP + ((idx & 15) << 2)] = val;
        }
    }
    __syncthreads();

    // ---- warp roles + Q fragments (hi/lo) ----
    const int rg = w & 1, cg = w >> 1;
    const int r0i = rg * 16 + g, r1i = r0i + 8;
    uint32_t ahh[4][4], alo[4][4];
#pragma unroll
    for (int s = 0; s < 4; s++) {
        int k0 = 16 * s + 2 * tq;
        float2 p00 = *(float2*)&Qs[r0i * QSP + k0];
        float2 p01 = *(float2*)&Qs[r0i * QSP + k0 + 8];
        float2 p10 = *(float2*)&Qs[r1i * QSP + k0];
        float2 p11 = *(float2*)&Qs[r1i * QSP + k0 + 8];
        ahh[s][0] = pack_hi(p00.x, p00.y); alo[s][0] = pack_lo(p00.x, p00.y, ahh[s][0]);
        ahh[s][1] = pack_hi(p10.x, p10.y); alo[s][1] = pack_lo(p10.x, p10.y, ahh[s][1]);
        ahh[s][2] = pack_hi(p01.x, p01.y); alo[s][2] = pack_lo(p01.x, p01.y, ahh[s][2]);
        ahh[s][3] = pack_hi(p11.x, p11.y); alo[s][3] = pack_lo(p11.x, p11.y, ahh[s][3]);
    }

    const size_t growBase = (size_t)b * LQ + q0;
    const size_t mrow0 = (growBase + r0i) * LK + cg * 16 + 2 * tq;
    const size_t mrow1 = mrow0 + 8 * (size_t)LK;

    uint32_t kmb = pack_mask8(km, mrow0, mrow1, 0);
    uint32_t qmb = pack_mask8(qm, mrow0, mrow1, 0);

    float Z0 = 0.0f, Z1 = 0.0f;
    char* e_r0 = sm + OFF_E + (r0i * PHS + (cg * 16 + 2 * tq)) * 2;
    char* e_r1 = e_r0 + 8 * (PHS * 2);

    // =================== Phase 1: E = exp(mask(Q K^T / 8)) ===================
    for (int c = 0; c < NCH; c++) {
        uint32_t kmn = 0, qmn = 0;
        if (c + 1 < NCH) {
            stage_tile(kb + (size_t)(c + 1) * TK * DD,
                       sbase + OFF_K0 + ((c + 1) % 3) * KBUF, t);
            CPA_COMMIT();
            // issue next-chunk mask loads BEFORE the wait so they fly under it
            int off = (c + 1) * TK;
            kmn = pack_mask8(km, mrow0, mrow1, off);
            qmn = pack_mask8(qm, mrow0, mrow1, off);
            CPA_WAIT1();
        } else {
            CPA_WAIT0();
        }
        __syncthreads();                       // buf c ready for all warps

        const char* kbuf = sm + OFF_K0 + (c % 3) * KBUF;
        float ac0[2][4], ac1[2][4];
#pragma unroll
        for (int nt = 0; nt < 2; nt++)
#pragma unroll
            for (int j = 0; j < 4; j++) { ac0[nt][j] = 0.0f; ac1[nt][j] = 0.0f; }

#pragma unroll
        for (int s = 0; s < 4; s++) {
#pragma unroll
            for (int nt = 0; nt < 2; nt++) {
                int row = cg * 16 + nt * 8 + g;
                int byte = (row * KS + 16 * s + 2 * tq) * 2;
                uint32_t bh0 = *(const uint32_t*)(kbuf + byte);
                uint32_t bh1 = *(const uint32_t*)(kbuf + byte + 16);
                mma16816(ac0[nt][0], ac0[nt][1], ac0[nt][2], ac0[nt][3],
                         ahh[s][0], ahh[s][1], ahh[s][2], ahh[s][3], bh0, bh1);
                mma16816(ac1[nt][0], ac1[nt][1], ac1[nt][2], ac1[nt][3],
                         alo[s][0], alo[s][1], alo[s][2], alo[s][3], bh0, bh1);
            }
        }

        // mask + exp + Z + fp16 E store
#pragma unroll
        for (int nt = 0; nt < 2; nt++) {
            float a0 = ac0[nt][0] + ac1[nt][0];
            float a1 = ac0[nt][1] + ac1[nt][1];
            float a2 = ac0[nt][2] + ac1[nt][2];
            float a3 = ac0[nt][3] + ac1[nt][3];
            float e00 = (kmb & (1u << (2 * nt)))  ? 0.0f : __expf(a0 * 0.125f);
            float e01 = (kmb & (2u << (2 * nt)))  ? 0.0f : __expf(a1 * 0.125f);
            float e10 = (kmb & (16u << (2 * nt))) ? 0.0f : __expf(a2 * 0.125f);
            float e11 = (kmb & (32u << (2 * nt))) ? 0.0f : __expf(a3 * 0.125f);
            Z0 += e00 + e01;
            Z1 += e10 + e11;
            float s00 = (qmb & (1u << (2 * nt)))  ? 0.0f : e00;
            float s01 = (qmb & (2u << (2 * nt)))  ? 0.0f : e01;
            float s10 = (qmb & (16u << (2 * nt))) ? 0.0f : e10;
            float s11 = (qmb & (32u << (2 * nt))) ? 0.0f : e11;
            int cofs = (c * TK + nt * 8) * 2;
            *(uint32_t*)(e_r0 + cofs) = pack_hi(s00, s01);
            *(uint32_t*)(e_r1 + cofs) = pack_hi(s10, s11);
        }
        kmb = kmn; qmb = qmn;
    }

    // ---- Z reduction ----
    Z0 += __shfl_xor_sync(0xffffffffu, Z0, 1);
    Z0 += __shfl_xor_sync(0xffffffffu, Z0, 2);
    Z1 += __shfl_xor_sync(0xffffffffu, Z1, 1);
    Z1 += __shfl_xor_sync(0xffffffffu, Z1, 2);
    if (tq == 0) {
        atomicAdd(&Zsm[r0i], Z0);
        atomicAdd(&Zsm[r1i], Z1);
    }
    __syncthreads();
    if (t < 32) Zsm[t] = 1.0f / Zsm[t];

    // issue V chunk 0 (K buf 0 free: all warps past phase-1 end)
    stage_tile(vb, sbase + OFF_K0, t);
    CPA_COMMIT();
    __syncthreads();                            // Zsm visible

    // ---- attn = E * invZ (overlaps V chunk-0 arrival) ----
    if (attn) {
#pragma unroll
        for (int rr = 0; rr < 4; rr++) {
            const int r = w + (rr << 3);
            const float invZ = Zsm[r];
            float* arow = attn + (growBase + r) * LK;
#pragma unroll
            for (int j = 0; j < 4; j++) {
                int col = 4 * l + 128 * j;
                uint2 hh = *(const uint2*)(sm + OFF_E + (r * PHS + col) * 2);
                float2 f0 = __half22float2(*(__half2*)&hh.x);
                float2 f1 = __half22float2(*(__half2*)&hh.y);
                *(float4*)(arow + col) = make_float4(f0.x * invZ, f0.y * invZ,
                                                     f1.x * invZ, f1.y * invZ);
            }
        }
    }

    // =================== Phase 2: O = (E V) * invZ ===================
    const int rg2 = w & 1, cg2 = w >> 1;
    float oe[2][4], oo[2][4];
#pragma unroll
    for (int nt = 0; nt < 2; nt++)
#pragma unroll
        for (int j = 0; j < 4; j++) { oe[nt][j] = 0.0f; oo[nt][j] = 0.0f; }

    const uint32_t a_base = sbase + OFF_E + (rg2 * 16 + (l & 15)) * (PHS * 2) + ((l >> 4) & 1) * 16;
    const uint32_t b_coloff = (cg2 * 16 + ((l >> 4) & 1) * 8) * 2;

    for (int c = 0; c < NCH; c++) {
        if (c + 1 < NCH) {
            stage_tile(vb + (size_t)(c + 1) * TK * DD,
                       sbase + OFF_K0 + ((c + 1) % 3) * KBUF, t);
            CPA_COMMIT();
            CPA_WAIT1();
        } else {
            CPA_WAIT0();
        }
        __syncthreads();

        const uint32_t vbuf = sbase + OFF_K0 + (c % 3) * KBUF;
#pragma unroll
        for (int s = 0; s < 4; s++) {
            uint32_t a0, a1, a2, a3, b0, b1, b2, b3;
            ldsm4(a0, a1, a2, a3, a_base + (c * TK + s * 16) * 2);
            ldsm4t(b0, b1, b2, b3, vbuf + (s * 16 + (l & 15)) * (KS * 2) + b_coloff);
            if (s & 1) {
                mma16816(oo[0][0], oo[0][1], oo[0][2], oo[0][3], a0, a1, a2, a3, b0, b1);
                mma16816(oo[1][0], oo[1][1], oo[1][2], oo[1][3], a0, a1, a2, a3, b2, b3);
            } else {
                mma16816(oe[0][0], oe[0][1], oe[0][2], oe[0][3], a0, a1, a2, a3, b0, b1);
                mma16816(oe[1][0], oe[1][1], oe[1][2], oe[1][3], a0, a1, a2, a3, b2, b3);
            }
        }
    }

    // write O with per-row 1/Z
    {
        const int row0 = rg2 * 16 + g;
        const float invZa = Zsm[row0], invZb = Zsm[row0 + 8];
#pragma unroll
        for (int nt = 0; nt < 2; nt++) {
            int col = cg2 * 16 + nt * 8 + 2 * tq;
            *(float2*)(out + (growBase + row0) * DD + col) =
                make_float2((oe[nt][0] + oo[nt][0]) * invZa, (oe[nt][1] + oo[nt][1]) * invZa);
            *(float2*)(out + (growBase + row0 + 8) * DD + col) =
                make_float2((oe[nt][2] + oo[nt][2]) * invZb, (oe[nt][3] + oo[nt][3]) * invZb);
        }
    }
}

extern "C" void kernel_launch(void* const* d_in, const int* in_sizes, int n_in,
                              void* d_out, int out_size)
{
    const float* q = (const float*)d_in[0];
    const float* k = (const float*)d_in[1];
    const float* v = (const float*)d_in[2];
    const int* km = (const int*)d_in[3];
    const int* qm = (const int*)d_in[4];

    const long long OUT_N  = (long long)BB * LQ * DD;
    const long long ATTN_N = (long long)BB * LQ * LK;

    float* out_p;
    float* attn_p;
    long long osz = (long long)out_size;
    if (osz >= OUT_N + ATTN_N) {
        out_p  = (float*)d_out;
        attn_p = (float*)d_out + OUT_N;
    } else if (osz == ATTN_N) {
        float* scratch;
        cudaGetSymbolAddress((void**)&scratch, g_out_scratch);
        out_p  = scratch;
        attn_p = (float*)d_out;
    } else {
        out_p  = (float*)d_out;
        attn_p = nullptr;
    }

    __half* khi_p;
    __half* vh_p;
    cudaGetSymbolAddress((void**)&khi_p, g_khi);
    cudaGetSymbolAddress((void**)&vh_p, g_vh);

    // prepass: K/V fp32 -> fp16 (once, grid-stride)
    cvt_kv_kernel<<<1024, 512>>>(k, v, khi_p, vh_p);

    cudaFuncSetAttribute(sdpa_flash_kernel, cudaFuncAttributeMaxDynamicSharedMemorySize, SMEM_BYTES);
    dim3 grid(LQ / TQ, BB);
    sdpa_flash_kernel<<<grid, NTHREADS, SMEM_BYTES>>>(q, khi_p, vh_p, km, qm, out_p, attn_p);
}

// round 17
// speedup vs baseline: 1.0908x; 1.0239x over previous
#include <cuda_runtime.h>
#include <cuda_fp16.h>
#include <cfloat>
#include <cstdint>

#define BB 128
#define LQ 512
#define LK 512
#define DD 64
#define TQ 64
#define TK 64
#define NCH (LK/TK)          // 8
#define PHS  520             // fp16 E stride (halves)
#define KS   72              // K/V fp16 row stride (halves) -> 144 B/row
#define QSP  68              // Q fp32 stride
#define NTHREADS 256

// smem byte offsets
#define OFF_E  0                           // 64*520*2 = 66560
#define KBUF   9216                        // 64*72*2
#define OFF_K0 66560                       // 3 buffers -> 27648
#define OFF_Q  (OFF_K0 + 3*KBUF)           // 94208, 64*68*4 = 17408
#define OFF_Z  (OFF_Q + 17408)             // 111616, 256
#define SMEM_BYTES (OFF_Z + 256)           // 111872 (x2 = 223744 <= 228KB)

__device__ float g_out_scratch[(size_t)BB * LQ * DD];
__device__ __half g_khi[(size_t)BB * LK * DD];   // 8 MB
__device__ __half g_vh [(size_t)BB * LK * DD];   // 8 MB

static __device__ __forceinline__ uint32_t s2u(const void* p) {
    uint32_t a;
    asm("{ .reg .u64 t; cvta.to.shared.u64 t, %1; cvt.u32.u64 %0, t; }" : "=r"(a) : "l"(p));
    return a;
}
static __device__ __forceinline__ uint32_t pack_hi(float x, float y) {
    __half2 h = __floats2half2_rn(x, y);
    return *(uint32_t*)&h;
}
static __device__ __forceinline__ uint32_t pack_lo(float x, float y, uint32_t hibits) {
    __half2 h = *(__half2*)&hibits;
    float2 hf = __half22float2(h);
    __half2 l = __floats2half2_rn(x - hf.x, y - hf.y);
    return *(uint32_t*)&l;
}
static __device__ __forceinline__ void mma16816(float& c0, float& c1, float& c2, float& c3,
                                                uint32_t a0, uint32_t a1, uint32_t a2, uint32_t a3,
                                                uint32_t b0, uint32_t b1) {
    asm volatile("mma.sync.aligned.m16n8k16.row.col.f32.f16.f16.f32 "
                 "{%0,%1,%2,%3}, {%4,%5,%6,%7}, {%8,%9}, {%0,%1,%2,%3};"
                 : "+f"(c0), "+f"(c1), "+f"(c2), "+f"(c3)
                 : "r"(a0), "r"(a1), "r"(a2), "r"(a3), "r"(b0), "r"(b1));
}
static __device__ __forceinline__ void ldsm4(uint32_t& r0, uint32_t& r1, uint32_t& r2, uint32_t& r3,
                                             uint32_t addr) {
    asm volatile("ldmatrix.sync.aligned.m8n8.x4.shared.b16 {%0,%1,%2,%3}, [%4];"
                 : "=r"(r0), "=r"(r1), "=r"(r2), "=r"(r3) : "r"(addr));
}
static __device__ __forceinline__ void ldsm4t(uint32_t& r0, uint32_t& r1, uint32_t& r2, uint32_t& r3,
                                              uint32_t addr) {
    asm volatile("ldmatrix.sync.aligned.m8n8.x4.trans.shared.b16 {%0,%1,%2,%3}, [%4];"
                 : "=r"(r0), "=r"(r1), "=r"(r2), "=r"(r3) : "r"(addr));
}
static __device__ __forceinline__ void cpa16(uint32_t dst, const void* src) {
    asm volatile("cp.async.ca.shared.global [%0], [%1], 16;" :: "r"(dst), "l"(src));
}
#define CPA_COMMIT() asm volatile("cp.async.commit_group;" ::: "memory")
#define CPA_WAIT0()  asm volatile("cp.async.wait_group 0;" ::: "memory")
#define CPA_WAIT1()  asm volatile("cp.async.wait_group 1;" ::: "memory")

// stage one 64x64 fp16 tile (row 128B in gmem -> stride 144B in smem), 2x16B per thread
static __device__ __forceinline__ void stage_tile(const __half* src, uint32_t dstbase, int t) {
    int row = t >> 2;
    int off = (t & 3) * 32;
    const char* s = (const char*)src + row * 128 + off;
    uint32_t d = dstbase + row * 144 + off;
    cpa16(d, s);
    cpa16(d + 16, s + 16);
}
// pack 16 mask bools (2 rows x 4 nt x 2 cols) into one bitmask
// row0 nt j -> bit (2*nt+j); row1 -> bit (8+2*nt+j)
static __device__ __forceinline__ uint32_t pack_mask16(const int* p, size_t r0, size_t r1, int off) {
    uint32_t m = 0;
#pragma unroll
    for (int nt = 0; nt < 4; nt++) {
        int2 a = *(const int2*)(p + r0 + off + nt * 8);
        int2 b = *(const int2*)(p + r1 + off + nt * 8);
        m |= (a.x ? 1u : 0u) << (2 * nt) | (a.y ? 2u : 0u) << (2 * nt)
           | (b.x ? 1u : 0u) << (8 + 2 * nt) | (b.y ? 2u : 0u) << (8 + 2 * nt);
    }
    return m;
}

// ---------------- prepass: fp32 -> fp16 for K and V (grid-stride) ----------------
__global__ void cvt_kv_kernel(const float* __restrict__ k, const float* __restrict__ v,
                              __half* __restrict__ kh, __half* __restrict__ vh) {
    const int n4 = BB * LK * DD / 4;
    for (int i = blockIdx.x * blockDim.x + threadIdx.x; i < n4; i += gridDim.x * blockDim.x) {
        float4 a = ((const float4*)k)[i];
        ((uint2*)kh)[i] = make_uint2(pack_hi(a.x, a.y), pack_hi(a.z, a.w));
        float4 b = ((const float4*)v)[i];
        ((uint2*)vh)[i] = make_uint2(pack_hi(b.x, b.y), pack_hi(b.z, b.w));
    }
}

__global__ __launch_bounds__(NTHREADS, 2)
void sdpa_flash_kernel(const float* __restrict__ q,
                       const __half* __restrict__ khi,
                       const __half* __restrict__ vh,
                       const int* __restrict__ km,
                       const int* __restrict__ qm,
                       float* __restrict__ out,
                       float* __restrict__ attn)
{
    extern __shared__ char sm[];
    const uint32_t sbase = s2u(sm);
    float* Qs  = (float*)(sm + OFF_Q);
    float* Zsm = (float*)(sm + OFF_Z);

    const int t = threadIdx.x;
    const int w = t >> 5, l = t & 31;
    const int g = l >> 2, tq = l & 3;
    const int b = blockIdx.y;
    const int q0 = blockIdx.x * TQ;

    const __half* kb = khi + (size_t)b * LK * DD;
    const __half* vb = vh + (size_t)b * LK * DD;

    if (t < TQ) Zsm[t] = 0.0f;

    // issue K chunk 0 via cp.async, then stage Q while it flies
    stage_tile(kb, sbase + OFF_K0, t);
    CPA_COMMIT();
    {
        const float4* qg = (const float4*)(q + ((size_t)b * LQ + q0) * DD);
#pragma unroll
        for (int i = 0; i < 4; i++) {
            int idx = t + NTHREADS * i;          // 0..1023
            float4 val = qg[idx];
            *(float4*)&Qs[(idx >> 4) * QSP + ((idx & 15) << 2)] = val;
        }
    }
    __syncthreads();

    // ---- warp roles: rg = 1 of 4 row-groups (16 rows), cg = 1 of 2 col-groups (32 k) ----
    const int rg = w & 3, cg = w >> 2;
    const int r0i = rg * 16 + g, r1i = r0i + 8;
    uint32_t ahh[4][4], alo[4][4];
#pragma unroll
    for (int s = 0; s < 4; s++) {
        int k0 = 16 * s + 2 * tq;
        float2 p00 = *(float2*)&Qs[r0i * QSP + k0];
        float2 p01 = *(float2*)&Qs[r0i * QSP + k0 + 8];
        float2 p10 = *(float2*)&Qs[r1i * QSP + k0];
        float2 p11 = *(float2*)&Qs[r1i * QSP + k0 + 8];
        ahh[s][0] = pack_hi(p00.x, p00.y); alo[s][0] = pack_lo(p00.x, p00.y, ahh[s][0]);
        ahh[s][1] = pack_hi(p10.x, p10.y); alo[s][1] = pack_lo(p10.x, p10.y, ahh[s][1]);
        ahh[s][2] = pack_hi(p01.x, p01.y); alo[s][2] = pack_lo(p01.x, p01.y, ahh[s][2]);
        ahh[s][3] = pack_hi(p11.x, p11.y); alo[s][3] = pack_lo(p11.x, p11.y, ahh[s][3]);
    }

    const size_t growBase = (size_t)b * LQ + q0;
    const size_t mrow0 = (growBase + r0i) * LK + cg * 32 + 2 * tq;
    const size_t mrow1 = mrow0 + 8 * (size_t)LK;

    uint32_t kmb = pack_mask16(km, mrow0, mrow1, 0);
    uint32_t qmb = pack_mask16(qm, mrow0, mrow1, 0);

    float Z0 = 0.0f, Z1 = 0.0f;
    char* e_r0 = sm + OFF_E + (r0i * PHS + (cg * 32 + 2 * tq)) * 2;
    char* e_r1 = e_r0 + 8 * (PHS * 2);

    // =================== Phase 1: E = exp(mask(Q K^T / 8)) ===================
    for (int c = 0; c < NCH; c++) {
        uint32_t kmn = 0, qmn = 0;
        if (c + 1 < NCH) {
            stage_tile(kb + (size_t)(c + 1) * TK * DD,
                       sbase + OFF_K0 + ((c + 1) % 3) * KBUF, t);
            CPA_COMMIT();
            int off = (c + 1) * TK;
            kmn = pack_mask16(km, mrow0, mrow1, off);
            qmn = pack_mask16(qm, mrow0, mrow1, off);
            CPA_WAIT1();
        } else {
            CPA_WAIT0();
        }
        __syncthreads();                       // buf c ready for all warps

        const char* kbuf = sm + OFF_K0 + (c % 3) * KBUF;
        float ac0[4][4], ac1[4][4];
#pragma unroll
        for (int nt = 0; nt < 4; nt++)
#pragma unroll
            for (int j = 0; j < 4; j++) { ac0[nt][j] = 0.0f; ac1[nt][j] = 0.0f; }

#pragma unroll
        for (int s = 0; s < 4; s++) {
#pragma unroll
            for (int nt = 0; nt < 4; nt++) {
                int row = cg * 32 + nt * 8 + g;
                int byte = (row * KS + 16 * s + 2 * tq) * 2;
                uint32_t bh0 = *(const uint32_t*)(kbuf + byte);
                uint32_t bh1 = *(const uint32_t*)(kbuf + byte + 16);
                mma16816(ac0[nt][0], ac0[nt][1], ac0[nt][2], ac0[nt][3],
                         ahh[s][0], ahh[s][1], ahh[s][2], ahh[s][3], bh0, bh1);
                mma16816(ac1[nt][0], ac1[nt][1], ac1[nt][2], ac1[nt][3],
                         alo[s][0], alo[s][1], alo[s][2], alo[s][3], bh0, bh1);
            }
        }

        // mask + exp + Z + fp16 E store
#pragma unroll
        for (int nt = 0; nt < 4; nt++) {
            float a0 = ac0[nt][0] + ac1[nt][0];
            float a1 = ac0[nt][1] + ac1[nt][1];
            float a2 = ac0[nt][2] + ac1[nt][2];
            float a3 = ac0[nt][3] + ac1[nt][3];
            float e00 = (kmb & (1u << (2 * nt)))     ? 0.0f : __expf(a0 * 0.125f);
            float e01 = (kmb & (2u << (2 * nt)))     ? 0.0f : __expf(a1 * 0.125f);
            float e10 = (kmb & (1u << (8 + 2 * nt))) ? 0.0f : __expf(a2 * 0.125f);
            float e11 = (kmb & (2u << (8 + 2 * nt))) ? 0.0f : __expf(a3 * 0.125f);
            Z0 += e00 + e01;
            Z1 += e10 + e11;
            float s00 = (qmb & (1u << (2 * nt)))     ? 0.0f : e00;
            float s01 = (qmb & (2u << (2 * nt)))     ? 0.0f : e01;
            float s10 = (qmb & (1u << (8 + 2 * nt))) ? 0.0f : e10;
            float s11 = (qmb & (2u << (8 + 2 * nt))) ? 0.0f : e11;
            int cofs = (c * TK + nt * 8) * 2;
            *(uint32_t*)(e_r0 + cofs) = pack_hi(s00, s01);
            *(uint32_t*)(e_r1 + cofs) = pack_hi(s10, s11);
        }
        kmb = kmn; qmb = qmn;
    }

    // ---- Z reduction ----
    Z0 += __shfl_xor_sync(0xffffffffu, Z0, 1);
    Z0 += __shfl_xor_sync(0xffffffffu, Z0, 2);
    Z1 += __shfl_xor_sync(0xffffffffu, Z1, 1);
    Z1 += __shfl_xor_sync(0xffffffffu, Z1, 2);
    if (tq == 0) {
        atomicAdd(&Zsm[r0i], Z0);
        atomicAdd(&Zsm[r1i], Z1);
    }
    __syncthreads();
    if (t < TQ) Zsm[t] = 1.0f / Zsm[t];

    // issue V chunk 0 (K buf 0 free: all warps past phase-1 end)
    stage_tile(vb, sbase + OFF_K0, t);
    CPA_COMMIT();
    __syncthreads();                            // Zsm visible

    // ---- attn = E * invZ (overlaps V chunk-0 arrival) ----
    if (attn) {
#pragma unroll
        for (int rr = 0; rr < 8; rr++) {
            const int r = w + (rr << 3);
            const float invZ = Zsm[r];
            float* arow = attn + (growBase + r) * LK;
#pragma unroll
            for (int j = 0; j < 4; j++) {
                int col = 4 * l + 128 * j;
                uint2 hh = *(const uint2*)(sm + OFF_E + (r * PHS + col) * 2);
                float2 f0 = __half22float2(*(__half2*)&hh.x);
                float2 f1 = __half22float2(*(__half2*)&hh.y);
                *(float4*)(arow + col) = make_float4(f0.x * invZ, f0.y * invZ,
                                                     f1.x * invZ, f1.y * invZ);
            }
        }
    }

    // =================== Phase 2: O = (E V) * invZ ===================
    // warp covers 16 rows (rg) x 32 out cols (cg); col tile idx 0..3 of 8 cols
    float oe[4][4], oo[4][4];
#pragma unroll
    for (int nt = 0; nt < 4; nt++)
#pragma unroll
        for (int j = 0; j < 4; j++) { oe[nt][j] = 0.0f; oo[nt][j] = 0.0f; }

    const uint32_t a_base = sbase + OFF_E + (rg * 16 + (l & 15)) * (PHS * 2) + ((l >> 4) & 1) * 16;
    const uint32_t b_col0 = (cg * 32 + ((l >> 4) & 1) * 8) * 2;

    for (int c = 0; c < NCH; c++) {
        if (c + 1 < NCH) {
            stage_tile(vb + (size_t)(c + 1) * TK * DD,
                       sbase + OFF_K0 + ((c + 1) % 3) * KBUF, t);
            CPA_COMMIT();
            CPA_WAIT1();
        } else {
            CPA_WAIT0();
        }
        __syncthreads();

        const uint32_t vbuf = sbase + OFF_K0 + (c % 3) * KBUF;
#pragma unroll
        for (int s = 0; s < 4; s++) {
            uint32_t a0, a1, a2, a3;
            ldsm4(a0, a1, a2, a3, a_base + (c * TK + s * 16) * 2);
#pragma unroll
            for (int h = 0; h < 2; h++) {
                uint32_t b0, b1, b2, b3;
                ldsm4t(b0, b1, b2, b3,
                       vbuf + (s * 16 + (l & 15)) * (KS * 2) + b_col0 + h * 32);
                if (s & 1) {
                    mma16816(oo[2*h][0], oo[2*h][1], oo[2*h][2], oo[2*h][3],
                             a0, a1, a2, a3, b0, b1);
                    mma16816(oo[2*h+1][0], oo[2*h+1][1], oo[2*h+1][2], oo[2*h+1][3],
                             a0, a1, a2, a3, b2, b3);
                } else {
                    mma16816(oe[2*h][0], oe[2*h][1], oe[2*h][2], oe[2*h][3],
                             a0, a1, a2, a3, b0, b1);
                    mma16816(oe[2*h+1][0], oe[2*h+1][1], oe[2*h+1][2], oe[2*h+1][3],
                             a0, a1, a2, a3, b2, b3);
                }
            }
        }
    }

    // write O with per-row 1/Z: cols = cg*32 + idx*8 + 2tq (idx = 2h + half)
    {
        const float invZa = Zsm[r0i], invZb = Zsm[r1i];
#pragma unroll
        for (int idx = 0; idx < 4; idx++) {
            int col = cg * 32 + idx * 8 + 2 * tq;
            *(float2*)(out + (growBase + r0i) * DD + col) =
                make_float2((oe[idx][0] + oo[idx][0]) * invZa, (oe[idx][1] + oo[idx][1]) * invZa);
            *(float2*)(out + (growBase + r1i) * DD + col) =
                make_float2((oe[idx][2] + oo[idx][2]) * invZb, (oe[idx][3] + oo[idx][3]) * invZb);
        }
    }
}

extern "C" void kernel_launch(void* const* d_in, const int* in_sizes, int n_in,
                              void* d_out, int out_size)
{
    const float* q = (const float*)d_in[0];
    const float* k = (const float*)d_in[1];
    const float* v = (const float*)d_in[2];
    const int* km = (const int*)d_in[3];
    const int* qm = (const int*)d_in[4];

    const long long OUT_N  = (long long)BB * LQ * DD;
    const long long ATTN_N = (long long)BB * LQ * LK;

    float* out_p;
    float* attn_p;
    long long osz = (long long)out_size;
    if (osz >= OUT_N + ATTN_N) {
        out_p  = (float*)d_out;
        attn_p = (float*)d_out + OUT_N;
    } else if (osz == ATTN_N) {
        float* scratch;
        cudaGetSymbolAddress((void**)&scratch, g_out_scratch);
        out_p  = scratch;
        attn_p = (float*)d_out;
    } else {
        out_p  = (float*)d_out;
        attn_p = nullptr;
    }

    __half* khi_p;
    __half* vh_p;
    cudaGetSymbolAddress((void**)&khi_p, g_khi);
    cudaGetSymbolAddress((void**)&vh_p, g_vh);

    // prepass: K/V fp32 -> fp16 (once, grid-stride)
    cvt_kv_kernel<<<1024, 512>>>(k, v, khi_p, vh_p);

    cudaFuncSetAttribute(sdpa_flash_kernel, cudaFuncAttributeMaxDynamicSharedMemorySize, SMEM_BYTES);
    dim3 grid(LQ / TQ, BB);
    sdpa_flash_kernel<<<grid, NTHREADS, SMEM_BYTES>>>(q, khi_p, vh_p, km, qm, out_p, attn_p);
}